// round 3
// baseline (speedup 1.0000x reference)
#include <cuda_runtime.h>
#include <cstdint>

// RVQ: B=32, T=4096, MEL=128, D=64, K=128. N = 131072 tokens.
// recon = dec0[i0] + dec1[i1]; i0/i1 from fused scores GEMM + Gram fold.

#define NTOK   (32 * 4096)
#define NTILE  (NTOK / 64)
#define NTHR   256

typedef unsigned long long ull;

// ---- packed fp32x2 helpers ----
__device__ __forceinline__ ull pack2(float lo, float hi) {
    ull r; asm("mov.b64 %0, {%1, %2};" : "=l"(r) : "f"(lo), "f"(hi)); return r;
}
__device__ __forceinline__ void unpack2(ull v, float& lo, float& hi) {
    asm("mov.b64 {%0, %1}, %2;" : "=f"(lo), "=f"(hi) : "l"(v));
}
__device__ __forceinline__ void ffma2(ull& d, ull a, ull b) {
    asm("fma.rn.f32x2 %0, %1, %2, %0;" : "+l"(d) : "l"(a), "l"(b));
}

// ---- precomputed tables (device globals; allocation-free scratch) ----
__device__ __align__(16) float g_twoG[128 * 128]; // 2 * cb0[j] . cb1[k]
__device__ __align__(16) float g_dec0[128 * 128]; // cb0[j] @ w_out^T + b_out
__device__ __align__(16) float g_dec1[128 * 128]; // cb1[j] @ w_out^T
__device__ __align__(16) float g_cT[64 * 256];    // cT[d][k]: k<128 -> cb0[k][d], else cb1[k-128][d]
__device__ __align__(16) float g_wT[128 * 64];    // wT[m][d] = w_in[d][m]
__device__ __align__(16) float g_c0n[128];
__device__ __align__(16) float g_c1n[128];

__device__ __forceinline__ float dot64(const float* __restrict__ a,
                                       const float* __restrict__ b) {
    float s = 0.f;
    const float4* b4 = (const float4*)b;
#pragma unroll
    for (int q = 0; q < 16; ++q) {
        float4 v = b4[q];
        s += a[4*q+0]*v.x + a[4*q+1]*v.y + a[4*q+2]*v.z + a[4*q+3]*v.w;
    }
    return s;
}

__global__ void rvq_precompute(const float* __restrict__ w_in,
                               const float* __restrict__ cb0,
                               const float* __restrict__ cb1,
                               const float* __restrict__ w_out,
                               const float* __restrict__ b_out) {
    __shared__ float c0r[64], c1r[64];
    const int j = blockIdx.x;      // 0..127
    const int t = threadIdx.x;     // 0..255
    if (t < 64)        c0r[t]      = cb0[j * 64 + t];
    else if (t < 128)  c1r[t - 64] = cb1[j * 64 + (t - 64)];
    __syncthreads();

    if (t < 128) {
        g_twoG[j * 128 + t] = 2.f * dot64(c0r, cb1 + t * 64);
        g_dec1[j * 128 + t] = dot64(c1r, w_out + t * 64);
        if (j < 64) {                       // wT: 8192 elems over 64 blocks
            int e = j * 128 + t;            // e = m*64 + d
            g_wT[e] = w_in[(e & 63) * 128 + (e >> 6)];
        }
    } else {
        int m = t - 128;
        g_dec0[j * 128 + m] = dot64(c0r, w_out + m * 64) + b_out[m];
        int e = j * 128 + m;                // cT: e = d*256 + k
        int d = e >> 8, k = e & 255;
        g_cT[e] = (k < 128) ? cb0[k * 64 + d] : cb1[(k - 128) * 64 + d];
    }
    if (t == 0)  { float s = 0.f; for (int d = 0; d < 64; ++d) s += c0r[d]*c0r[d]; g_c0n[j] = s; }
    if (t == 32) { float s = 0.f; for (int d = 0; d < 64; ++d) s += c1r[d]*c1r[d]; g_c1n[j] = s; }
}

// ---- smem layout (floats) ----
// region A [0,16640): phase1 = mel[64][132] (8448) + wT [128][16 float4] (8192)
//                     phase2 = cT[64][64 float4] (16384, XOR chunk swizzle)
// Z [16640,20992): z[64][68]
// pv [20992,21504)  pk(int) [21504,22016)  i0s [22016,22080)  i1s [22080,22144)
#define OFF_W   8448
#define OFF_Z   16640
#define OFF_PV  20992
#define OFF_PK  21504
#define OFF_I0  22016
#define OFF_I1  22080
#define SMEM_FLOATS 22144
#define SMEM_BYTES  (SMEM_FLOATS * 4)

__global__ void __launch_bounds__(NTHR, 2)
rvq_main(const float* __restrict__ mel, const float* __restrict__ b_in,
         float* __restrict__ out) {
    extern __shared__ float sm[];
    float*  smMel = sm;                       // stride 132
    float4* smW4  = (float4*)(sm + OFF_W);    // [m][16] chunks
    float4* smC4  = (float4*)sm;              // [d][64] chunks (swizzled)
    float*  smZ   = sm + OFF_Z;               // stride 68
    float*  pv    = sm + OFF_PV;              // [64 tok][8]
    int*    pk    = (int*)(sm + OFF_PK);
    int*    i0s   = (int*)(sm + OFF_I0);
    int*    i1s   = (int*)(sm + OFF_I1);

    const int tid  = threadIdx.x;
    const int tile = blockIdx.x;

    // ---- stage mel (64x128) + wT ----
    {
        const float4* mg = (const float4*)(mel + (size_t)tile * (64 * 128));
#pragma unroll
        for (int r = 0; r < 8; ++r) {
            int f = tid + NTHR * r;            // 0..2047 float4
            int tk = f >> 5, m4 = f & 31;
            *(float4*)(smMel + tk * 132 + m4 * 4) = mg[f];
        }
        const float4* wg = (const float4*)g_wT;
#pragma unroll
        for (int r = 0; r < 8; ++r) { int f = tid + NTHR * r; smW4[f] = wg[f]; }
    }
    __syncthreads();

    // ---- phase 1: z = mel @ w_in^T + b_in. 2 tok x 8 d, packed f32x2 ----
    {
        const int kq8 = tid & 7;          // 0..7
        const int t0  = (tid >> 3) * 2;   // 0,2,..,62
        ull acc[2][2][2];
        {
            const float4* b4 = (const float4*)b_in;
            float4 bj0 = b4[kq8], bj1 = b4[8 + kq8];
#pragma unroll
            for (int i = 0; i < 2; ++i) {
                acc[i][0][0] = pack2(bj0.x, bj0.y); acc[i][0][1] = pack2(bj0.z, bj0.w);
                acc[i][1][0] = pack2(bj1.x, bj1.y); acc[i][1][1] = pack2(bj1.z, bj1.w);
            }
        }
        const float* m0 = smMel + t0 * 132;
        const float* m1 = smMel + (t0 + 1) * 132;
        const ulonglong2* w2 = (const ulonglong2*)smW4;
#pragma unroll 4
        for (int m = 0; m < 128; ++m) {
            ull p0 = pack2(m0[m], m0[m]);
            ull p1 = pack2(m1[m], m1[m]);
            ulonglong2 w0 = w2[m * 16 + kq8];
            ulonglong2 w1 = w2[m * 16 + 8 + kq8];
            ffma2(acc[0][0][0], p0, w0.x); ffma2(acc[0][0][1], p0, w0.y);
            ffma2(acc[0][1][0], p0, w1.x); ffma2(acc[0][1][1], p0, w1.y);
            ffma2(acc[1][0][0], p1, w0.x); ffma2(acc[1][0][1], p1, w0.y);
            ffma2(acc[1][1][0], p1, w1.x); ffma2(acc[1][1][1], p1, w1.y);
        }
#pragma unroll
        for (int i = 0; i < 2; ++i)
#pragma unroll
            for (int j = 0; j < 2; ++j) {
                *(ull*)(smZ + (t0 + i) * 68 + kq8 * 4 + 32 * j)     = acc[i][j][0];
                *(ull*)(smZ + (t0 + i) * 68 + kq8 * 4 + 32 * j + 2) = acc[i][j][1];
            }
    }
    __syncthreads();  // z done; region A free

    // ---- stage cT with chunk swizzle: phys = c ^ ((c>>3)&7) ----
    {
        const float4* cg = (const float4*)g_cT;
#pragma unroll
        for (int r = 0; r < 16; ++r) {
            int f = tid + NTHR * r;            // 0..4095 float4
            int d = f >> 6, c = f & 63;
            smC4[d * 64 + (c ^ ((c >> 3) & 7))] = cg[f];
        }
    }
    __syncthreads();

    // ---- phase 2: scores, 4 tok x 16 k per thread, packed f32x2 ----
    const int kg   = tid & 15;          // k group: k = kg*16 + kk
    const int tg   = tid >> 4;          // 0..15
    const int tok0 = tg * 4;
    const int cx   = (kg >> 1) & 7;     // swizzle xor for this thread's chunks
    const int cb   = kg * 4;            // logical chunk base

    ull acc[4][8];                      // [tok][pair]: pair p covers kk = (p>>1)*4 + (p&1)*2 + {0,1}
#pragma unroll
    for (int i = 0; i < 4; ++i)
#pragma unroll
        for (int p = 0; p < 8; ++p) acc[i][p] = 0ull;

#pragma unroll 2
    for (int dq = 0; dq < 16; ++dq) {   // d = dq*4 + dd
        float4 z4[4];
#pragma unroll
        for (int i = 0; i < 4; ++i)
            z4[i] = *(const float4*)(smZ + (tok0 + i) * 68 + dq * 4);
#pragma unroll
        for (int dd = 0; dd < 4; ++dd) {
            const ulonglong2* crow = (const ulonglong2*)(smC4 + (dq * 4 + dd) * 64);
            float zc[4] = { dd == 0 ? z4[0].x : dd == 1 ? z4[0].y : dd == 2 ? z4[0].z : z4[0].w,
                            dd == 0 ? z4[1].x : dd == 1 ? z4[1].y : dd == 2 ? z4[1].z : z4[1].w,
                            dd == 0 ? z4[2].x : dd == 1 ? z4[2].y : dd == 2 ? z4[2].z : z4[2].w,
                            dd == 0 ? z4[3].x : dd == 1 ? z4[3].y : dd == 2 ? z4[3].z : z4[3].w };
            ull zp[4];
#pragma unroll
            for (int i = 0; i < 4; ++i) zp[i] = pack2(zc[i], zc[i]);
#pragma unroll
            for (int j = 0; j < 4; ++j) {
                ulonglong2 cc = crow[(cb + j) ^ cx];
#pragma unroll
                for (int i = 0; i < 4; ++i) {
                    ffma2(acc[i][j * 2],     zp[i], cc.x);
                    ffma2(acc[i][j * 2 + 1], zp[i], cc.y);
                }
            }
        }
    }

    // ---- level-0 argmin (kg < 8 owns k = kg*16 + kk) ----
    if (kg < 8) {
        float n[16];
#pragma unroll
        for (int q = 0; q < 4; ++q) {
            float4 v = *(const float4*)(g_c0n + kg * 16 + q * 4);
            n[4*q] = v.x; n[4*q+1] = v.y; n[4*q+2] = v.z; n[4*q+3] = v.w;
        }
#pragma unroll
        for (int i = 0; i < 4; ++i) {
            float su[16];
#pragma unroll
            for (int j = 0; j < 4; ++j) {
                unpack2(acc[i][2*j],   su[4*j],   su[4*j+1]);
                unpack2(acc[i][2*j+1], su[4*j+2], su[4*j+3]);
            }
            float best = 3.402823466e38f; int bi = 0;
#pragma unroll
            for (int kk = 0; kk < 16; ++kk) {
                float v = n[kk] - 2.f * su[kk];
                if (v < best) { best = v; bi = kg * 16 + kk; }
            }
            pv[(tok0 + i) * 8 + kg] = best;
            pk[(tok0 + i) * 8 + kg] = bi;
        }
    }
    __syncthreads();
    if (tid < 64) {
        float best = pv[tid * 8]; int bi = pk[tid * 8];
#pragma unroll
        for (int q = 1; q < 8; ++q) {
            float v = pv[tid * 8 + q];
            if (v < best) { best = v; bi = pk[tid * 8 + q]; }
        }
        i0s[tid] = bi;
    }
    __syncthreads();

    // ---- level-1 argmin (kg >= 8 owns k1 = (kg-8)*16 + kk) with Gram fold ----
    if (kg >= 8) {
        const int kg1 = kg - 8;
        float n[16];
#pragma unroll
        for (int q = 0; q < 4; ++q) {
            float4 v = *(const float4*)(g_c1n + kg1 * 16 + q * 4);
            n[4*q] = v.x; n[4*q+1] = v.y; n[4*q+2] = v.z; n[4*q+3] = v.w;
        }
#pragma unroll
        for (int i = 0; i < 4; ++i) {
            const float* grow = g_twoG + i0s[tok0 + i] * 128 + kg1 * 16;
            float g[16];
#pragma unroll
            for (int q = 0; q < 4; ++q) {
                float4 v = *(const float4*)(grow + q * 4);
                g[4*q] = v.x; g[4*q+1] = v.y; g[4*q+2] = v.z; g[4*q+3] = v.w;
            }
            float su[16];
#pragma unroll
            for (int j = 0; j < 4; ++j) {
                unpack2(acc[i][2*j],   su[4*j],   su[4*j+1]);
                unpack2(acc[i][2*j+1], su[4*j+2], su[4*j+3]);
            }
            float best = 3.402823466e38f; int bi = 0;
#pragma unroll
            for (int kk = 0; kk < 16; ++kk) {
                float v = n[kk] - 2.f * su[kk] + g[kk];
                if (v < best) { best = v; bi = kg1 * 16 + kk; }
            }
            pv[(tok0 + i) * 8 + kg1] = best;
            pk[(tok0 + i) * 8 + kg1] = bi;
        }
    }
    __syncthreads();
    if (tid < 64) {
        float best = pv[tid * 8]; int bi = pk[tid * 8];
#pragma unroll
        for (int q = 1; q < 8; ++q) {
            float v = pv[tid * 8 + q];
            if (v < best) { best = v; bi = pk[tid * 8 + q]; }
        }
        i1s[tid] = bi;
    }
    __syncthreads();

    // ---- phase 3: out = dec0[i0] + dec1[i1] (coalesced float4) ----
    {
        const float4* d0 = (const float4*)g_dec0;
        const float4* d1 = (const float4*)g_dec1;
        float4* o4 = (float4*)out + (size_t)tile * 2048;
#pragma unroll
        for (int r = 0; r < 8; ++r) {
            int f = tid + NTHR * r;            // 0..2047
            int tok = f >> 5, m4 = f & 31;
            float4 a = d0[i0s[tok] * 32 + m4];
            float4 b = d1[i1s[tok] * 32 + m4];
            o4[f] = make_float4(a.x + b.x, a.y + b.y, a.z + b.z, a.w + b.w);
        }
    }
}

extern "C" void kernel_launch(void* const* d_in, const int* in_sizes, int n_in,
                              void* d_out, int out_size) {
    const float* mel   = (const float*)d_in[0];
    const float* w_in  = (const float*)d_in[1];
    const float* b_in  = (const float*)d_in[2];
    const float* cb0   = (const float*)d_in[3];
    const float* cb1   = (const float*)d_in[4];
    const float* w_out = (const float*)d_in[5];
    const float* b_out = (const float*)d_in[6];
    float* out = (float*)d_out;

    cudaFuncSetAttribute(rvq_main, cudaFuncAttributeMaxDynamicSharedMemorySize, SMEM_BYTES);

    rvq_precompute<<<128, NTHR>>>(w_in, cb0, cb1, w_out, b_out);
    rvq_main<<<NTILE, NTHR, SMEM_BYTES>>>(mel, b_in, out);
}

// round 7
// speedup vs baseline: 1.4721x; 1.4721x over previous
#include <cuda_runtime.h>
#include <cstdint>

// RVQ: B=32, T=4096, MEL=128, D=64, K=128. N = 131072 tokens.
// recon = dec0[i0] + dec1[i1]; i0/i1 from fused scores GEMM + Gram fold.

#define NTOK   (32 * 4096)
#define NTILE  (NTOK / 64)
#define NTHR   256

// ---- precomputed tables (device globals; allocation-free scratch) ----
__device__ __align__(16) float g_twoG[128 * 128]; // 2 * cb0[j] . cb1[k]
__device__ __align__(16) float g_dec0[128 * 128]; // cb0[j] @ w_out^T + b_out
__device__ __align__(16) float g_dec1[128 * 128]; // cb1[j] @ w_out^T
__device__ __align__(16) float g_cT[64 * 256];    // cT[d][k]: k<128 -> cb0[k][d], else cb1[k-128][d]
__device__ __align__(16) float g_wT[128 * 64];    // wT[m][d] = w_in[d][m]
__device__ __align__(16) float g_c0n[128];
__device__ __align__(16) float g_c1n[128];

__device__ __forceinline__ float dot64(const float* __restrict__ a,
                                       const float* __restrict__ b) {
    float s = 0.f;
    const float4* b4 = (const float4*)b;
#pragma unroll
    for (int q = 0; q < 16; ++q) {
        float4 v = b4[q];
        s += a[4*q+0]*v.x + a[4*q+1]*v.y + a[4*q+2]*v.z + a[4*q+3]*v.w;
    }
    return s;
}

__global__ void rvq_precompute(const float* __restrict__ w_in,
                               const float* __restrict__ cb0,
                               const float* __restrict__ cb1,
                               const float* __restrict__ w_out,
                               const float* __restrict__ b_out) {
    __shared__ float c0r[64], c1r[64];
    const int j = blockIdx.x;      // 0..127
    const int t = threadIdx.x;     // 0..255
    if (t < 64)        c0r[t]      = cb0[j * 64 + t];
    else if (t < 128)  c1r[t - 64] = cb1[j * 64 + (t - 64)];
    __syncthreads();

    if (t < 128) {
        g_twoG[j * 128 + t] = 2.f * dot64(c0r, cb1 + t * 64);
        g_dec1[j * 128 + t] = dot64(c1r, w_out + t * 64);
        if (j < 64) {                       // wT: 8192 elems over 64 blocks
            int e = j * 128 + t;            // e = m*64 + d
            g_wT[e] = w_in[(e & 63) * 128 + (e >> 6)];
        }
    } else {
        int m = t - 128;
        g_dec0[j * 128 + m] = dot64(c0r, w_out + m * 64) + b_out[m];
        int e = j * 128 + m;                // cT: e = d*256 + k
        int d = e >> 8, k = e & 255;
        g_cT[e] = (k < 128) ? cb0[k * 64 + d] : cb1[(k - 128) * 64 + d];
    }
    if (t == 0)  { float s = 0.f; for (int d = 0; d < 64; ++d) s += c0r[d]*c0r[d]; g_c0n[j] = s; }
    if (t == 32) { float s = 0.f; for (int d = 0; d < 64; ++d) s += c1r[d]*c1r[d]; g_c1n[j] = s; }
}

// ---- smem layout (floats) ----
// region A [0,16640): phase1 = mel[64][132] (8448) + wT [128][16 f4] (8192)
//                     phase2 = cT[64][64 f4] (16384)
//                     argmin = pv[64][32] (2048) + pk[64][32] (2048)
// Z [16640,20992): z[64][68]
// i0s [20992,21056)  i1s [21056,21120)
#define OFF_W   8448
#define OFF_Z   16640
#define OFF_PK  2048
#define OFF_I0  20992
#define OFF_I1  21056
#define SMEM_FLOATS 21120
#define SMEM_BYTES  (SMEM_FLOATS * 4)

__global__ void __launch_bounds__(NTHR, 2)
rvq_main(const float* __restrict__ mel, const float* __restrict__ b_in,
         float* __restrict__ out) {
    extern __shared__ float sm[];
    float*  smMel = sm;                       // stride 132
    float4* smW4  = (float4*)(sm + OFF_W);    // [m][16]
    float4* smC4  = (float4*)sm;              // [d][64]
    float*  smZ   = sm + OFF_Z;               // stride 68
    float*  pv    = sm;                       // [tok][32] (after cT is dead)
    int*    pk    = (int*)(sm + OFF_PK);      // [tok][32]
    int*    i0s   = (int*)(sm + OFF_I0);
    int*    i1s   = (int*)(sm + OFF_I1);

    const int tid  = threadIdx.x;
    const int tile = blockIdx.x;

    // ---- stage mel (64x128, padded stride 132) + wT ----
    {
        const float4* mg = (const float4*)(mel + (size_t)tile * (64 * 128));
#pragma unroll
        for (int r = 0; r < 8; ++r) {
            int f = tid + NTHR * r;            // 0..2047 float4
            int tk = f >> 5, m4 = f & 31;
            *(float4*)(smMel + tk * 132 + m4 * 4) = mg[f];
        }
        const float4* wg = (const float4*)g_wT;
#pragma unroll
        for (int r = 0; r < 8; ++r) { int f = tid + NTHR * r; smW4[f] = wg[f]; }
    }
    __syncthreads();

    // ---- phase 1: z = mel @ w_in^T + b_in.  4 tok x 4 d per thread ----
    {
        const int tg = tid >> 4;          // token group: tokens tg*4..+3
        const int dg = tid & 15;          // d group: d = dg*4..+3
        float acc[4][4];
        {
            float4 b4 = *(const float4*)(b_in + dg * 4);
#pragma unroll
            for (int i = 0; i < 4; ++i) {
                acc[i][0] = b4.x; acc[i][1] = b4.y; acc[i][2] = b4.z; acc[i][3] = b4.w;
            }
        }
#pragma unroll 4
        for (int mq = 0; mq < 32; ++mq) {
            float4 a4[4];
#pragma unroll
            for (int i = 0; i < 4; ++i)
                a4[i] = *(const float4*)(smMel + (tg * 4 + i) * 132 + mq * 4);
            const float* a = (const float*)a4;   // a[i*4+mm]
#pragma unroll
            for (int mm = 0; mm < 4; ++mm) {
                float4 w = smW4[(mq * 4 + mm) * 16 + dg];
#pragma unroll
                for (int i = 0; i < 4; ++i) {
                    float av = a[i * 4 + mm];
                    acc[i][0] += av * w.x; acc[i][1] += av * w.y;
                    acc[i][2] += av * w.z; acc[i][3] += av * w.w;
                }
            }
        }
#pragma unroll
        for (int i = 0; i < 4; ++i)
            *(float4*)(smZ + (tg * 4 + i) * 68 + dg * 4) =
                make_float4(acc[i][0], acc[i][1], acc[i][2], acc[i][3]);
    }
    __syncthreads();  // z done; region A free

    // ---- stage cT (plain copy; [d][64 float4], conflict-free by layout) ----
    {
        const float4* cg = (const float4*)g_cT;
#pragma unroll
        for (int r = 0; r < 16; ++r) { int f = tid + NTHR * r; smC4[f] = cg[f]; }
    }
    __syncthreads();

    // ---- phase 2: scores. warp = 8 tokens x 256 k; thread = 8 tok x (4 k0 + 4 k1)
    const int lane = tid & 31;
    const int wrp  = tid >> 5;
    const int tok0 = wrp * 8;

    float a0[8][4], a1[8][4];
#pragma unroll
    for (int t = 0; t < 8; ++t)
#pragma unroll
        for (int j = 0; j < 4; ++j) { a0[t][j] = 0.f; a1[t][j] = 0.f; }

    {
        const float* zb = smZ + tok0 * 68;
#pragma unroll 2
        for (int d = 0; d < 64; ++d) {
            const float4* rowC = smC4 + d * 64;
            float4 c0 = rowC[lane];
            float4 c1 = rowC[32 + lane];
#pragma unroll
            for (int t = 0; t < 8; ++t) {
                float zv = zb[t * 68 + d];
                a0[t][0] += zv * c0.x; a0[t][1] += zv * c0.y;
                a0[t][2] += zv * c0.z; a0[t][3] += zv * c0.w;
                a1[t][0] += zv * c1.x; a1[t][1] += zv * c1.y;
                a1[t][2] += zv * c1.z; a1[t][3] += zv * c1.w;
            }
        }
    }
    __syncthreads();   // cT dead; region A becomes pv/pk

    // ---- level-0 argmin: thread-local over its 4 k0, then lane scan ----
    {
        float4 n0 = *(const float4*)(g_c0n + lane * 4);
        float nn[4] = {n0.x, n0.y, n0.z, n0.w};
#pragma unroll
        for (int t = 0; t < 8; ++t) {
            float best = 3.402823466e38f; int bi = 0;
#pragma unroll
            for (int j = 0; j < 4; ++j) {
                float v = nn[j] - 2.f * a0[t][j];
                if (v < best) { best = v; bi = lane * 4 + j; }
            }
            pv[(tok0 + t) * 32 + lane] = best;
            pk[(tok0 + t) * 32 + lane] = bi;
        }
    }
    __syncthreads();
    if (tid < 64) {
        float best = pv[tid * 32]; int bi = pk[tid * 32];
#pragma unroll 8
        for (int l = 1; l < 32; ++l) {
            float v = pv[tid * 32 + l];
            if (v < best) { best = v; bi = pk[tid * 32 + l]; }
        }
        i0s[tid] = bi;
    }
    __syncthreads();

    // ---- level-1 argmin with Gram fold (twoG rows from L2) ----
    {
        float4 n1 = *(const float4*)(g_c1n + lane * 4);
        float nn[4] = {n1.x, n1.y, n1.z, n1.w};
#pragma unroll
        for (int t = 0; t < 8; ++t) {
            float4 g4 = *(const float4*)(g_twoG + i0s[tok0 + t] * 128 + lane * 4);
            float gg[4] = {g4.x, g4.y, g4.z, g4.w};
            float best = 3.402823466e38f; int bi = 0;
#pragma unroll
            for (int j = 0; j < 4; ++j) {
                float v = nn[j] - 2.f * a1[t][j] + gg[j];
                if (v < best) { best = v; bi = lane * 4 + j; }
            }
            pv[(tok0 + t) * 32 + lane] = best;
            pk[(tok0 + t) * 32 + lane] = bi;
        }
    }
    __syncthreads();
    if (tid < 64) {
        float best = pv[tid * 32]; int bi = pk[tid * 32];
#pragma unroll 8
        for (int l = 1; l < 32; ++l) {
            float v = pv[tid * 32 + l];
            if (v < best) { best = v; bi = pk[tid * 32 + l]; }
        }
        i1s[tid] = bi;
    }
    __syncthreads();

    // ---- phase 3: out = dec0[i0] + dec1[i1] (coalesced float4) ----
    {
        const float4* d0 = (const float4*)g_dec0;
        const float4* d1 = (const float4*)g_dec1;
        float4* o4 = (float4*)out + (size_t)tile * 2048;
#pragma unroll
        for (int r = 0; r < 8; ++r) {
            int f = tid + NTHR * r;            // 0..2047
            int tok = f >> 5, m4 = f & 31;
            float4 a = d0[i0s[tok] * 32 + m4];
            float4 b = d1[i1s[tok] * 32 + m4];
            o4[f] = make_float4(a.x + b.x, a.y + b.y, a.z + b.z, a.w + b.w);
        }
    }
}

extern "C" void kernel_launch(void* const* d_in, const int* in_sizes, int n_in,
                              void* d_out, int out_size) {
    const float* mel   = (const float*)d_in[0];
    const float* w_in  = (const float*)d_in[1];
    const float* b_in  = (const float*)d_in[2];
    const float* cb0   = (const float*)d_in[3];
    const float* cb1   = (const float*)d_in[4];
    const float* w_out = (const float*)d_in[5];
    const float* b_out = (const float*)d_in[6];
    float* out = (float*)d_out;

    cudaFuncSetAttribute(rvq_main, cudaFuncAttributeMaxDynamicSharedMemorySize, SMEM_BYTES);

    rvq_precompute<<<128, NTHR>>>(w_in, cb0, cb1, w_out, b_out);
    rvq_main<<<NTILE, NTHR, SMEM_BYTES>>>(mel, b_in, out);
}

// round 8
// speedup vs baseline: 1.5634x; 1.0620x over previous
#include <cuda_runtime.h>
#include <cstdint>

// RVQ: B=32, T=4096, MEL=128, D=64, K=128. N = 131072 tokens.
// recon = dec0[i0] + dec1[i1]; i0/i1 from fused scores GEMM + Gram fold.

#define NTOK   (32 * 4096)
#define NTILE  (NTOK / 64)
#define NTHR   256

// ---- precomputed tables (device globals; allocation-free scratch) ----
__device__ __align__(16) float g_twoG[128 * 128]; // 2 * cb0[j] . cb1[k]
__device__ __align__(16) float g_dec0[128 * 128]; // cb0[j] @ w_out^T + b_out
__device__ __align__(16) float g_dec1[128 * 128]; // cb1[j] @ w_out^T
__device__ __align__(16) float g_cT[64 * 256];    // cT[d][k]: k<128 -> cb0[k][d], else cb1[k-128][d]
__device__ __align__(16) float g_wT[128 * 64];    // wT[m][d] = w_in[d][m]
__device__ __align__(16) float g_c0n[128];
__device__ __align__(16) float g_c1n[128];

__device__ __forceinline__ float dot64(const float* __restrict__ a,
                                       const float* __restrict__ b) {
    float s = 0.f;
    const float4* b4 = (const float4*)b;
#pragma unroll
    for (int q = 0; q < 16; ++q) {
        float4 v = b4[q];
        s += a[4*q+0]*v.x + a[4*q+1]*v.y + a[4*q+2]*v.z + a[4*q+3]*v.w;
    }
    return s;
}

__global__ void rvq_precompute(const float* __restrict__ w_in,
                               const float* __restrict__ cb0,
                               const float* __restrict__ cb1,
                               const float* __restrict__ w_out,
                               const float* __restrict__ b_out) {
    __shared__ float c0r[64], c1r[64];
    const int j = blockIdx.x;      // 0..127
    const int t = threadIdx.x;     // 0..255
    if (t < 64)        c0r[t]      = cb0[j * 64 + t];
    else if (t < 128)  c1r[t - 64] = cb1[j * 64 + (t - 64)];
    __syncthreads();

    if (t < 128) {
        g_twoG[j * 128 + t] = 2.f * dot64(c0r, cb1 + t * 64);
        g_dec1[j * 128 + t] = dot64(c1r, w_out + t * 64);
        if (j < 64) {                       // wT: 8192 elems over 64 blocks
            int e = j * 128 + t;            // e = m*64 + d
            g_wT[e] = w_in[(e & 63) * 128 + (e >> 6)];
        }
    } else {
        int m = t - 128;
        g_dec0[j * 128 + m] = dot64(c0r, w_out + m * 64) + b_out[m];
        int e = j * 128 + m;                // cT: e = d*256 + k
        int d = e >> 8, k = e & 255;
        g_cT[e] = (k < 128) ? cb0[k * 64 + d] : cb1[(k - 128) * 64 + d];
    }
    if (t == 0)  { float s = 0.f; for (int d = 0; d < 64; ++d) s += c0r[d]*c0r[d]; g_c0n[j] = s; }
    if (t == 32) { float s = 0.f; for (int d = 0; d < 64; ++d) s += c1r[d]*c1r[d]; g_c1n[j] = s; }
}

// ---- smem layout (floats) ----
// region A [0,12544): phase1 = mel[64][132] (8448) + wT chunk [64][16 f4] (4096)
//                     phase2 = cT half [64][32 f4] (8192)
//                     argmin = pv[64][32] (2048) + pk[64][32] (2048)
// Z [12544,16896): z[64][68]
// i0s [16896,16960)  i1s [16960,17024)
#define OFF_W   8448
#define OFF_Z   12544
#define OFF_I0  16896
#define OFF_I1  16960
#define SMEM_FLOATS 17024
#define SMEM_BYTES  (SMEM_FLOATS * 4)

__global__ void __launch_bounds__(NTHR, 3)
rvq_main(const float* __restrict__ mel, const float* __restrict__ b_in,
         float* __restrict__ out) {
    extern __shared__ float sm[];
    float*  smMel = sm;                       // [64][132]
    float4* smW4  = (float4*)(sm + OFF_W);    // [64 m][16]
    float4* smC4  = (float4*)sm;              // [64 d][32] (phase 2 halves)
    float*  smZ   = sm + OFF_Z;               // [64][68]
    float*  pv    = sm;                       // [64][32] (overlay, after cT half dead)
    int*    pk    = (int*)(sm + 2048);        // [64][32]
    int*    i0s   = (int*)(sm + OFF_I0);
    int*    i1s   = (int*)(sm + OFF_I1);

    const int tid  = threadIdx.x;
    const int tile = blockIdx.x;
    const int lane = tid & 31;
    const int wrp  = tid >> 5;
    const int tok0 = wrp * 8;

    // ---- stage mel (64x128, stride 132) + wT chunk 0 ----
    {
        const float4* mg = (const float4*)(mel + (size_t)tile * (64 * 128));
#pragma unroll
        for (int r = 0; r < 8; ++r) {
            int f = tid + NTHR * r;            // 0..2047 float4
            int tk = f >> 5, m4 = f & 31;
            *(float4*)(smMel + tk * 132 + m4 * 4) = mg[f];
        }
        const float4* wg = (const float4*)g_wT;
#pragma unroll
        for (int r = 0; r < 4; ++r) { int f = tid + NTHR * r; smW4[f] = wg[f]; }
    }
    __syncthreads();

    // ---- phase 1: z = mel @ w_in^T + b_in.  4 tok x 4 d, two m-chunks ----
    {
        const int tg = tid >> 4;          // tokens tg*4..+3
        const int dg = tid & 15;          // d = dg*4..+3
        float acc[4][4];
        {
            float4 b4 = *(const float4*)(b_in + dg * 4);
#pragma unroll
            for (int i = 0; i < 4; ++i) {
                acc[i][0] = b4.x; acc[i][1] = b4.y; acc[i][2] = b4.z; acc[i][3] = b4.w;
            }
        }
#pragma unroll
        for (int ch = 0; ch < 2; ++ch) {
            if (ch == 1) {
                __syncthreads();          // chunk-0 reads complete
                const float4* wg = (const float4*)g_wT + 1024;
#pragma unroll
                for (int r = 0; r < 4; ++r) { int f = tid + NTHR * r; smW4[f] = wg[f]; }
                __syncthreads();
            }
#pragma unroll 4
            for (int mq = 0; mq < 16; ++mq) {
                float4 a4[4];
#pragma unroll
                for (int i = 0; i < 4; ++i)
                    a4[i] = *(const float4*)(smMel + (tg * 4 + i) * 132 + ch * 64 + mq * 4);
                const float* a = (const float*)a4;   // a[i*4+mm]
#pragma unroll
                for (int mm = 0; mm < 4; ++mm) {
                    float4 w = smW4[(mq * 4 + mm) * 16 + dg];
#pragma unroll
                    for (int i = 0; i < 4; ++i) {
                        float av = a[i * 4 + mm];
                        acc[i][0] += av * w.x; acc[i][1] += av * w.y;
                        acc[i][2] += av * w.z; acc[i][3] += av * w.w;
                    }
                }
            }
        }
#pragma unroll
        for (int i = 0; i < 4; ++i)
            *(float4*)(smZ + (tg * 4 + i) * 68 + dg * 4) =
                make_float4(acc[i][0], acc[i][1], acc[i][2], acc[i][3]);
    }
    __syncthreads();   // z ready; region A free

    float a[8][4];
    const float4* cg4 = (const float4*)g_cT;

    // =========== pass A: level-0 scores (k = lane*4 + j) ===========
    {
#pragma unroll
        for (int r = 0; r < 8; ++r) {       // stage cT cols [0,128)
            int f = tid + NTHR * r;          // 0..2047
            smC4[f] = cg4[(f >> 5) * 64 + (f & 31)];
        }
    }
    __syncthreads();
#pragma unroll
    for (int t = 0; t < 8; ++t)
#pragma unroll
        for (int j = 0; j < 4; ++j) a[t][j] = 0.f;
    {
        const float* zb = smZ + tok0 * 68;
#pragma unroll 2
        for (int dq = 0; dq < 16; ++dq) {
            float4 z4[8];
#pragma unroll
            for (int t = 0; t < 8; ++t)
                z4[t] = *(const float4*)(zb + t * 68 + dq * 4);
#pragma unroll
            for (int dd = 0; dd < 4; ++dd) {
                float4 c = smC4[(dq * 4 + dd) * 32 + lane];
#pragma unroll
                for (int t = 0; t < 8; ++t) {
                    float zv = ((const float*)&z4[t])[dd];
                    a[t][0] += zv * c.x; a[t][1] += zv * c.y;
                    a[t][2] += zv * c.z; a[t][3] += zv * c.w;
                }
            }
        }
    }
    __syncthreads();   // cT half dead -> pv/pk
    {
        float4 n0 = *(const float4*)(g_c0n + lane * 4);
        float nn[4] = {n0.x, n0.y, n0.z, n0.w};
#pragma unroll
        for (int t = 0; t < 8; ++t) {
            float best = 3.402823466e38f; int bi = 0;
#pragma unroll
            for (int j = 0; j < 4; ++j) {
                float v = nn[j] - 2.f * a[t][j];
                if (v < best) { best = v; bi = lane * 4 + j; }
            }
            pv[(tok0 + t) * 32 + lane] = best;
            pk[(tok0 + t) * 32 + lane] = bi;
        }
    }
    __syncthreads();
    if (tid < 64) {
        float best = pv[tid * 32]; int bi = pk[tid * 32];
#pragma unroll 8
        for (int l = 1; l < 32; ++l) {
            float v = pv[tid * 32 + l];
            if (v < best) { best = v; bi = pk[tid * 32 + l]; }
        }
        i0s[tid] = bi;
    }
    __syncthreads();

    // =========== pass B: level-1 scores + Gram fold ===========
    {
#pragma unroll
        for (int r = 0; r < 8; ++r) {       // stage cT cols [128,256)
            int f = tid + NTHR * r;
            smC4[f] = cg4[(f >> 5) * 64 + 32 + (f & 31)];
        }
    }
    __syncthreads();
#pragma unroll
    for (int t = 0; t < 8; ++t)
#pragma unroll
        for (int j = 0; j < 4; ++j) a[t][j] = 0.f;
    {
        const float* zb = smZ + tok0 * 68;
#pragma unroll 2
        for (int dq = 0; dq < 16; ++dq) {
            float4 z4[8];
#pragma unroll
            for (int t = 0; t < 8; ++t)
                z4[t] = *(const float4*)(zb + t * 68 + dq * 4);
#pragma unroll
            for (int dd = 0; dd < 4; ++dd) {
                float4 c = smC4[(dq * 4 + dd) * 32 + lane];
#pragma unroll
                for (int t = 0; t < 8; ++t) {
                    float zv = ((const float*)&z4[t])[dd];
                    a[t][0] += zv * c.x; a[t][1] += zv * c.y;
                    a[t][2] += zv * c.z; a[t][3] += zv * c.w;
                }
            }
        }
    }
    __syncthreads();   // cT half dead -> pv/pk
    {
        float4 n1 = *(const float4*)(g_c1n + lane * 4);
        float nn[4] = {n1.x, n1.y, n1.z, n1.w};
#pragma unroll
        for (int t = 0; t < 8; ++t) {
            float4 g4 = *(const float4*)(g_twoG + i0s[tok0 + t] * 128 + lane * 4);
            float best = 3.402823466e38f; int bi = 0;
            float vv[4] = {nn[0] - 2.f * a[t][0] + g4.x,
                           nn[1] - 2.f * a[t][1] + g4.y,
                           nn[2] - 2.f * a[t][2] + g4.z,
                           nn[3] - 2.f * a[t][3] + g4.w};
#pragma unroll
            for (int j = 0; j < 4; ++j)
                if (vv[j] < best) { best = vv[j]; bi = lane * 4 + j; }
            pv[(tok0 + t) * 32 + lane] = best;
            pk[(tok0 + t) * 32 + lane] = bi;
        }
    }
    __syncthreads();
    if (tid < 64) {
        float best = pv[tid * 32]; int bi = pk[tid * 32];
#pragma unroll 8
        for (int l = 1; l < 32; ++l) {
            float v = pv[tid * 32 + l];
            if (v < best) { best = v; bi = pk[tid * 32 + l]; }
        }
        i1s[tid] = bi;
    }
    __syncthreads();

    // ---- phase 3: out = dec0[i0] + dec1[i1] (coalesced float4) ----
    {
        const float4* d0 = (const float4*)g_dec0;
        const float4* d1 = (const float4*)g_dec1;
        float4* o4 = (float4*)out + (size_t)tile * 2048;
#pragma unroll
        for (int r = 0; r < 8; ++r) {
            int f = tid + NTHR * r;            // 0..2047
            int tok = f >> 5, m4 = f & 31;
            float4 va = d0[i0s[tok] * 32 + m4];
            float4 vb = d1[i1s[tok] * 32 + m4];
            o4[f] = make_float4(va.x + vb.x, va.y + vb.y, va.z + vb.z, va.w + vb.w);
        }
    }
}

extern "C" void kernel_launch(void* const* d_in, const int* in_sizes, int n_in,
                              void* d_out, int out_size) {
    const float* mel   = (const float*)d_in[0];
    const float* w_in  = (const float*)d_in[1];
    const float* b_in  = (const float*)d_in[2];
    const float* cb0   = (const float*)d_in[3];
    const float* cb1   = (const float*)d_in[4];
    const float* w_out = (const float*)d_in[5];
    const float* b_out = (const float*)d_in[6];
    float* out = (float*)d_out;

    cudaFuncSetAttribute(rvq_main, cudaFuncAttributeMaxDynamicSharedMemorySize, SMEM_BYTES);

    rvq_precompute<<<128, NTHR>>>(w_in, cb0, cb1, w_out, b_out);
    rvq_main<<<NTILE, NTHR, SMEM_BYTES>>>(mel, b_in, out);
}